// round 1
// baseline (speedup 1.0000x reference)
#include <cuda_runtime.h>

#define F_IN 512
#define HID  64
#define NCLS 16
#define NMAX 100000

// ---------------- scratch (static device globals; no allocation) -------------
__device__ float g_h1[NMAX * HID];   // x @ W1^T
__device__ float g_a1[NMAX * HID];   // aggregated layer-1 (pre-bias/relu)
__device__ float g_h2[NMAX * NCLS];  // relu(a1+b1) @ W2^T
__device__ float g_deg[NMAX];        // deg, then dinv (in place)

// ---------------- small PTX helpers ------------------------------------------
__device__ __forceinline__ unsigned long long pack2(float lo, float hi) {
    unsigned long long r;
    asm("mov.b64 %0, {%1, %2};" : "=l"(r) : "f"(lo), "f"(hi));
    return r;
}
__device__ __forceinline__ void unpack2(unsigned long long v, float& lo, float& hi) {
    asm("mov.b64 {%0, %1}, %2;" : "=f"(lo), "=f"(hi) : "l"(v));
}
__device__ __forceinline__ unsigned long long fma2(unsigned long long a,
                                                   unsigned long long b,
                                                   unsigned long long c) {
    unsigned long long d;
    asm("fma.rn.f32x2 %0, %1, %2, %3;" : "=l"(d) : "l"(a), "l"(b), "l"(c));
    return d;
}
__device__ __forceinline__ void red4(float* addr, float a, float b, float c, float d) {
    asm volatile("red.global.add.v4.f32 [%0], {%1, %2, %3, %4};"
                 :: "l"(addr), "f"(a), "f"(b), "f"(c), "f"(d) : "memory");
}

// ---------------- degree / normalization -------------------------------------
__global__ void k_deg_init(int N) {
    int i = blockIdx.x * blockDim.x + threadIdx.x;
    if (i < N) g_deg[i] = 1.0f;  // self-loop weight
}
__global__ void k_deg_accum(const int* __restrict__ col, const float* __restrict__ ew, int E) {
    int i = blockIdx.x * blockDim.x + threadIdx.x;
    if (i < E) atomicAdd(&g_deg[col[i]], ew[i]);
}
__global__ void k_dinv(int N) {
    int i = blockIdx.x * blockDim.x + threadIdx.x;
    if (i < N) {
        float d = g_deg[i];
        g_deg[i] = (d > 0.0f) ? rsqrtf(d) : 0.0f;
    }
}

// ---------------- GEMM1: h1[N,64] = x[N,512] @ W1[64,512]^T ------------------
// BM=256 rows/block, BN=64 (all outputs), BK=16. 256 threads, 8x8 per thread,
// f32x2 packed FMA (pairs along M).
__global__ void __launch_bounds__(256) k_gemm1(const float* __restrict__ x,
                                               const float* __restrict__ W1, int N) {
    __shared__ float As[16][256];  // [k][m] transposed
    __shared__ float Bs[16][64];   // [k][n] transposed

    int tid = threadIdx.x;
    int tx = tid & 7;        // 0..7  -> n0 = tx*8
    int ty = tid >> 3;       // 0..31 -> m0 = ty*8
    int m0 = ty * 8;
    int n0 = tx * 8;
    int bm = blockIdx.x * 256;

    unsigned long long acc[4][8];
#pragma unroll
    for (int p = 0; p < 4; p++)
#pragma unroll
        for (int j = 0; j < 8; j++) acc[p][j] = 0ull;

    for (int k0 = 0; k0 < F_IN; k0 += 16) {
        // load x tile (256x16), transposed into As[k][m]; 4 float4 per thread
#pragma unroll
        for (int i = 0; i < 4; i++) {
            int idx = tid + i * 256;     // 0..1023
            int r   = idx >> 2;          // 0..255
            int c4  = (idx & 3) * 4;     // 0,4,8,12
            float4 v = make_float4(0.f, 0.f, 0.f, 0.f);
            int gr = bm + r;
            if (gr < N) v = *(const float4*)(x + (size_t)gr * F_IN + k0 + c4);
            As[c4 + 0][r] = v.x; As[c4 + 1][r] = v.y;
            As[c4 + 2][r] = v.z; As[c4 + 3][r] = v.w;
        }
        // load W1 tile (64x16), transposed into Bs[k][n]; 1 float4 per thread
        {
            int r  = tid >> 2;           // 0..63
            int c4 = (tid & 3) * 4;
            float4 v = *(const float4*)(W1 + (size_t)r * F_IN + k0 + c4);
            Bs[c4 + 0][r] = v.x; Bs[c4 + 1][r] = v.y;
            Bs[c4 + 2][r] = v.z; Bs[c4 + 3][r] = v.w;
        }
        __syncthreads();

#pragma unroll
        for (int k = 0; k < 16; k++) {
            unsigned long long a[4];
#pragma unroll
            for (int p = 0; p < 4; p++)
                a[p] = *(const unsigned long long*)&As[k][m0 + 2 * p];
            float4 w0 = *(const float4*)&Bs[k][n0];
            float4 w1 = *(const float4*)&Bs[k][n0 + 4];
            unsigned long long bb[8];
            bb[0] = pack2(w0.x, w0.x); bb[1] = pack2(w0.y, w0.y);
            bb[2] = pack2(w0.z, w0.z); bb[3] = pack2(w0.w, w0.w);
            bb[4] = pack2(w1.x, w1.x); bb[5] = pack2(w1.y, w1.y);
            bb[6] = pack2(w1.z, w1.z); bb[7] = pack2(w1.w, w1.w);
#pragma unroll
            for (int p = 0; p < 4; p++)
#pragma unroll
                for (int j = 0; j < 8; j++)
                    acc[p][j] = fma2(a[p], bb[j], acc[p][j]);
        }
        __syncthreads();
    }

    // write h1: rows bm+m0+2p (+1), cols n0..n0+7
#pragma unroll
    for (int p = 0; p < 4; p++) {
        float lo[8], hi[8];
#pragma unroll
        for (int j = 0; j < 8; j++) unpack2(acc[p][j], lo[j], hi[j]);
        int r0 = bm + m0 + 2 * p;
        if (r0 < N) {
            float4* o = (float4*)(g_h1 + (size_t)r0 * HID + n0);
            o[0] = make_float4(lo[0], lo[1], lo[2], lo[3]);
            o[1] = make_float4(lo[4], lo[5], lo[6], lo[7]);
        }
        if (r0 + 1 < N) {
            float4* o = (float4*)(g_h1 + (size_t)(r0 + 1) * HID + n0);
            o[0] = make_float4(hi[0], hi[1], hi[2], hi[3]);
            o[1] = make_float4(hi[4], hi[5], hi[6], hi[7]);
        }
    }
}

// ---------------- layer-1 aggregation ----------------------------------------
// self-loop init: a1[i] = h1[i] * dinv[i]^2
__global__ void k_agg1_init(int N) {
    int idx = blockIdx.x * blockDim.x + threadIdx.x;  // over N*16 float4s
    if (idx >= N * 16) return;
    int i = idx >> 4;
    float di = g_deg[i];
    float s = di * di;
    float4 v = *(const float4*)(g_h1 + (size_t)idx * 4);
    v.x *= s; v.y *= s; v.z *= s; v.w *= s;
    *(float4*)(g_a1 + (size_t)idx * 4) = v;
}
// 16 threads per edge; lane (t==0) of each group loads indices + norm, shfl-broadcast
__global__ void k_agg1_edge(const int* __restrict__ rowi, const int* __restrict__ coli,
                            const float* __restrict__ ew, int E) {
    int idx = blockIdx.x * blockDim.x + threadIdx.x;
    int e = idx >> 4;
    int t = idx & 15;
    bool valid = (e < E);
    if (e >= E) e = E - 1;  // keep all lanes active for shfl
    int lane = threadIdx.x & 31;
    int src = lane & 16;  // group leader lane (0 or 16)
    int r = 0, c = 0; float nrm = 0.f;
    if ((lane & 15) == 0) {
        r = rowi[e]; c = coli[e];
        nrm = g_deg[r] * ew[e] * g_deg[c];
    }
    r   = __shfl_sync(0xFFFFFFFFu, r, src);
    c   = __shfl_sync(0xFFFFFFFFu, c, src);
    nrm = __shfl_sync(0xFFFFFFFFu, nrm, src);
    float4 h = *(const float4*)(g_h1 + (size_t)r * HID + t * 4);
    if (valid)
        red4(g_a1 + (size_t)c * HID + t * 4, h.x * nrm, h.y * nrm, h.z * nrm, h.w * nrm);
}

// ---------------- GEMM2: h2[N,16] = relu(a1+b1)[N,64] @ W2[16,64]^T ----------
__global__ void __launch_bounds__(256) k_gemm2(const float* __restrict__ W2,
                                               const float* __restrict__ b1, int N) {
    __shared__ float Ws[NCLS * HID];  // 1024 floats
    __shared__ float bs[HID];
    int tid = threadIdx.x;
    for (int i = tid; i < NCLS * HID; i += 256) Ws[i] = W2[i];
    if (tid < HID) bs[tid] = b1[tid];
    __syncthreads();

    int i  = blockIdx.x * 64 + (tid >> 2);
    int co = (tid & 3) * 4;
    if (i >= N) return;

    float a0 = 0.f, a1v = 0.f, a2 = 0.f, a3 = 0.f;
    const float4* rowp = (const float4*)(g_a1 + (size_t)i * HID);
#pragma unroll
    for (int k4 = 0; k4 < 16; k4++) {
        float4 v  = rowp[k4];
        float4 bv = *(const float4*)&bs[k4 * 4];
        v.x = fmaxf(v.x + bv.x, 0.f);
        v.y = fmaxf(v.y + bv.y, 0.f);
        v.z = fmaxf(v.z + bv.z, 0.f);
        v.w = fmaxf(v.w + bv.w, 0.f);
        float4 w0 = *(const float4*)&Ws[(co + 0) * HID + k4 * 4];
        float4 w1 = *(const float4*)&Ws[(co + 1) * HID + k4 * 4];
        float4 w2 = *(const float4*)&Ws[(co + 2) * HID + k4 * 4];
        float4 w3 = *(const float4*)&Ws[(co + 3) * HID + k4 * 4];
        a0 += v.x * w0.x + v.y * w0.y + v.z * w0.z + v.w * w0.w;
        a1v += v.x * w1.x + v.y * w1.y + v.z * w1.z + v.w * w1.w;
        a2 += v.x * w2.x + v.y * w2.y + v.z * w2.z + v.w * w2.w;
        a3 += v.x * w3.x + v.y * w3.y + v.z * w3.z + v.w * w3.w;
    }
    *(float4*)(g_h2 + (size_t)i * NCLS + co) = make_float4(a0, a1v, a2, a3);
}

// ---------------- layer-2 aggregation (into d_out) ---------------------------
__global__ void k_agg2_init(float* __restrict__ out, int N) {
    int idx = blockIdx.x * blockDim.x + threadIdx.x;  // over N*4 float4s
    if (idx >= N * 4) return;
    int i = idx >> 2;
    float di = g_deg[i];
    float s = di * di;
    float4 v = *(const float4*)(g_h2 + (size_t)idx * 4);
    v.x *= s; v.y *= s; v.z *= s; v.w *= s;
    *(float4*)(out + (size_t)idx * 4) = v;
}
// 4 threads per edge
__global__ void k_agg2_edge(const int* __restrict__ rowi, const int* __restrict__ coli,
                            const float* __restrict__ ew, float* __restrict__ out, int E) {
    int idx = blockIdx.x * blockDim.x + threadIdx.x;
    int e = idx >> 2;
    int t = idx & 3;
    bool valid = (e < E);
    if (e >= E) e = E - 1;
    int lane = threadIdx.x & 31;
    int src = lane & 28;  // leader of each 4-lane group
    int r = 0, c = 0; float nrm = 0.f;
    if ((lane & 3) == 0) {
        r = rowi[e]; c = coli[e];
        nrm = g_deg[r] * ew[e] * g_deg[c];
    }
    r   = __shfl_sync(0xFFFFFFFFu, r, src);
    c   = __shfl_sync(0xFFFFFFFFu, c, src);
    nrm = __shfl_sync(0xFFFFFFFFu, nrm, src);
    float4 h = *(const float4*)(g_h2 + (size_t)r * NCLS + t * 4);
    if (valid)
        red4(out + (size_t)c * NCLS + t * 4, h.x * nrm, h.y * nrm, h.z * nrm, h.w * nrm);
}

// ---------------- bias + log_softmax (in place on d_out) ---------------------
__global__ void k_finalize(float* __restrict__ out, const float* __restrict__ b2, int N) {
    int i = blockIdx.x * blockDim.x + threadIdx.x;
    if (i >= N) return;
    float v[NCLS];
    const float4* p = (const float4*)(out + (size_t)i * NCLS);
#pragma unroll
    for (int q = 0; q < 4; q++) {
        float4 t = p[q];
        v[q * 4 + 0] = t.x + __ldg(b2 + q * 4 + 0);
        v[q * 4 + 1] = t.y + __ldg(b2 + q * 4 + 1);
        v[q * 4 + 2] = t.z + __ldg(b2 + q * 4 + 2);
        v[q * 4 + 3] = t.w + __ldg(b2 + q * 4 + 3);
    }
    float m = v[0];
#pragma unroll
    for (int q = 1; q < NCLS; q++) m = fmaxf(m, v[q]);
    float s = 0.f;
#pragma unroll
    for (int q = 0; q < NCLS; q++) s += expf(v[q] - m);
    float l = m + logf(s);
    float4* o = (float4*)(out + (size_t)i * NCLS);
#pragma unroll
    for (int q = 0; q < 4; q++)
        o[q] = make_float4(v[q * 4 + 0] - l, v[q * 4 + 1] - l,
                           v[q * 4 + 2] - l, v[q * 4 + 3] - l);
}

// ---------------- launch ------------------------------------------------------
extern "C" void kernel_launch(void* const* d_in, const int* in_sizes, int n_in,
                              void* d_out, int out_size) {
    const float* x  = (const float*)d_in[0];
    const int*   ei = (const int*)d_in[1];
    const float* ea = (const float*)d_in[2];
    const float* W1 = (const float*)d_in[3];
    const float* b1 = (const float*)d_in[4];
    const float* W2 = (const float*)d_in[5];
    const float* b2 = (const float*)d_in[6];
    float* out = (float*)d_out;

    int N = in_sizes[0] / F_IN;
    int E = in_sizes[2];
    const int* rowp = ei;       // edge_index[0] = source
    const int* colp = ei + E;   // edge_index[1] = target

    int tb = 256;
    k_deg_init<<<(N + tb - 1) / tb, tb>>>(N);
    k_deg_accum<<<(E + tb - 1) / tb, tb>>>(colp, ea, E);
    k_dinv<<<(N + tb - 1) / tb, tb>>>(N);

    k_gemm1<<<(N + 255) / 256, 256>>>(x, W1, N);

    k_agg1_init<<<(N * 16 + tb - 1) / tb, tb>>>(N);
    {
        long long total = (long long)E * 16;
        k_agg1_edge<<<(int)((total + tb - 1) / tb), tb>>>(rowp, colp, ea, E);
    }

    k_gemm2<<<(N + 63) / 64, 256>>>(W2, b1, N);

    k_agg2_init<<<(N * 4 + tb - 1) / tb, tb>>>(out, N);
    {
        long long total = (long long)E * 4;
        k_agg2_edge<<<(int)((total + tb - 1) / tb), tb>>>(rowp, colp, ea, out, E);
    }

    k_finalize<<<(N + tb - 1) / tb, tb>>>(out, b2, N);
}